// round 12
// baseline (speedup 1.0000x reference)
#include <cuda_runtime.h>
#include <cstdint>
#include <cstddef>

// ---------------------------------------------------------------- shapes
constexpr int Bb  = 128;
constexpr int Nn  = 256;
constexpr int Cch = 512;
constexpr int Oo  = 256;
constexpr int MR  = Bb * Nn;   // 32768
constexpr int C3  = 3 * Cch;   // 1536
constexpr int C2  = 2 * Cch;   // 1024

// ---------------------------------------------------------------- scratch
__device__ float g_msg [(size_t)MR * Cch];   //  64 MB
__device__ float g_gzr [(size_t)MR * C2];    // 134 MB  (xz+hz | xr+hr)
__device__ float g_xh  [(size_t)MR * Cch];   //  67 MB
__device__ float g_hnew[(size_t)MR * Cch];   //  64 MB

// ---------------------------------------------------------------- helpers
__device__ __forceinline__ uint32_t smem_u32(const void* p) {
    uint32_t a;
    asm("{ .reg .u64 t; cvta.to.shared.u64 t, %1; cvt.u32.u64 %0, t; }" : "=r"(a) : "l"(p));
    return a;
}
__device__ __forceinline__ uint32_t f2tf(float f) {
    uint32_t u;
    asm("cvt.rna.tf32.f32 %0, %1;" : "=r"(u) : "f"(f));
    return u;
}
__device__ __forceinline__ void cp16(uint32_t saddr, const float* g) {
    asm volatile("cp.async.cg.shared.global [%0], [%1], 16;" :: "r"(saddr), "l"(g));
}
#define CP_COMMIT() asm volatile("cp.async.commit_group;" ::: "memory")
#define CP_WAIT1()  asm volatile("cp.async.wait_group 1;"  ::: "memory")

__device__ __forceinline__ void mma8(float* c, const uint32_t* a, const uint32_t* b) {
    asm volatile(
        "mma.sync.aligned.m16n8k8.row.col.f32.tf32.tf32.f32 "
        "{%0,%1,%2,%3}, {%4,%5,%6,%7}, {%8,%9}, {%0,%1,%2,%3};\n"
        : "+f"(c[0]), "+f"(c[1]), "+f"(c[2]), "+f"(c[3])
        : "r"(a[0]), "r"(a[1]), "r"(a[2]), "r"(a[3]),
          "r"(b[0]), "r"(b[1]));
}
// sigmoid / tanh via fast exp only (EX2+RCP class, <=2 ULP on exp)
__device__ __forceinline__ float sigf(float x) { return 1.f / (1.f + __expf(-x)); }
__device__ __forceinline__ float tanhfast(float x) {
    return 2.f / (1.f + __expf(-2.f * x)) - 1.f;
}

// ---------------------------------------------------------------- GEMM
// CTA 128x128, 8 warps (2x4), warp 64x32, BK=32, 3-stage cp.async, 2 CTA/SM.
// DUAL : C = A1@B1 + A2@B2 + bias1 + bias2   (two K-passes, shared lda/ldb)
// GATES: C(=hnew) = gru_gate(gzr, xh, acc+bias1, ann) fused epilogue
constexpr int BM = 128, BN = 128, BK = 32;
constexpr int ASTR = BK + 4;    // 36
constexpr int BSTR = BN + 8;    // 136
constexpr int STAGES = 3;
constexpr int ASZ = BM * ASTR;
constexpr int BSZ = BK * BSTR;
constexpr int SMEM_BYTES = STAGES * (ASZ + BSZ) * 4;   // 107520 B

template<bool DUAL, bool GATES>
__global__ __launch_bounds__(256, 2)
void gemm_k(const float* __restrict__ A1, const float* __restrict__ B1, int T1,
            const float* __restrict__ A2, const float* __restrict__ B2, int T2,
            float* __restrict__ C,
            const float* __restrict__ bias1, const float* __restrict__ bias2,
            int lda, int ldb, int ldc,
            long long sA, long long sB, long long sC,
            const float* __restrict__ gzr, const float* __restrict__ xh,
            const float* __restrict__ ann)
{
    extern __shared__ float sm[];
    float* As = sm;
    float* Bs = sm + STAGES * ASZ;
    const uint32_t sbA = smem_u32(As);
    const uint32_t sbB = smem_u32(Bs);

    A1 += (long long)blockIdx.z * sA;
    B1 += (long long)blockIdx.z * sB;
    C  += (long long)blockIdx.z * sC;

    const int tid  = threadIdx.x;
    const int lane = tid & 31;
    const int warp = tid >> 5;
    const int wm   = warp >> 2;
    const int wn   = warp & 3;
    const int row0 = blockIdx.y * BM;
    const int col0 = blockIdx.x * BN;

    const int arow = tid >> 3;            // 0..31 (+32i)
    const int acol = (tid & 7) * 4;
    const int brow = tid >> 5;            // 0..7  (+8i)
    const int bcol = (tid & 31) * 4;

    const float* aG1 = A1 + (size_t)(row0 + arow) * lda + acol;
    const float* bG1 = B1 + (size_t)brow * ldb + (col0 + bcol);
    const float* aG2 = DUAL ? A2 + (size_t)(row0 + arow) * lda + acol : nullptr;
    const float* bG2 = DUAL ? B2 + (size_t)brow * ldb + (col0 + bcol) : nullptr;

    uint32_t aS[4], bS[4];
#pragma unroll
    for (int i = 0; i < 4; i++) {
        aS[i] = sbA + (uint32_t)((arow + 32 * i) * ASTR + acol) * 4u;
        bS[i] = sbB + (uint32_t)((brow + 8 * i) * BSTR + bcol) * 4u;
    }

    auto issue = [&](int kt, int s) {
        const float *ag, *bg;
        if (DUAL && kt >= T1) {
            const int k2 = kt - T1;
            ag = aG2 + (size_t)k2 * BK;
            bg = bG2 + (size_t)k2 * BK * ldb;
        } else {
            ag = aG1 + (size_t)kt * BK;
            bg = bG1 + (size_t)kt * BK * ldb;
        }
#pragma unroll
        for (int i = 0; i < 4; i++)
            cp16(aS[i] + s * (ASZ * 4), ag + (size_t)(32 * i) * lda);
#pragma unroll
        for (int i = 0; i < 4; i++)
            cp16(bS[i] + s * (BSZ * 4), bg + (size_t)(8 * i) * ldb);
    };

    const int T = DUAL ? (T1 + T2) : T1;

    float acc[4][4][4];
#pragma unroll
    for (int mi = 0; mi < 4; mi++)
#pragma unroll
        for (int ni = 0; ni < 4; ni++)
#pragma unroll
            for (int r = 0; r < 4; r++) acc[mi][ni][r] = 0.f;

    issue(0, 0); CP_COMMIT();
    issue(1, 1); CP_COMMIT();

    int use_s = 0, fill_s = 2;
    for (int kt = 0; kt < T; kt++) {
        CP_WAIT1();
        __syncthreads();

        if (kt + 2 < T) issue(kt + 2, fill_s);
        CP_COMMIT();

        const float* as = As + use_s * ASZ;
        const float* bs = Bs + use_s * BSZ;
#pragma unroll
        for (int kk = 0; kk < BK; kk += 8) {
            uint32_t af[4][4], bf[4][2];
#pragma unroll
            for (int mi = 0; mi < 4; mi++) {
                const int r  = wm * 64 + mi * 16 + (lane >> 2);
                const int cc = kk + (lane & 3);
                af[mi][0] = f2tf(as[ r      * ASTR + cc    ]);
                af[mi][1] = f2tf(as[(r + 8) * ASTR + cc    ]);
                af[mi][2] = f2tf(as[ r      * ASTR + cc + 4]);
                af[mi][3] = f2tf(as[(r + 8) * ASTR + cc + 4]);
            }
#pragma unroll
            for (int ni = 0; ni < 4; ni++) {
                const int cc = wn * 32 + ni * 8 + (lane >> 2);
                const int kr = kk + (lane & 3);
                bf[ni][0] = f2tf(bs[ kr      * BSTR + cc]);
                bf[ni][1] = f2tf(bs[(kr + 4) * BSTR + cc]);
            }
#pragma unroll
            for (int mi = 0; mi < 4; mi++)
#pragma unroll
                for (int ni = 0; ni < 4; ni++)
                    mma8(acc[mi][ni], af[mi], bf[ni]);
        }

        if (++use_s  == STAGES) use_s  = 0;
        if (++fill_s == STAGES) fill_s = 0;
    }

    // ---------------- epilogue ----------------
    // hoist per-thread bias values (gc depends on ni only)
    float bv0[4], bv1[4];
#pragma unroll
    for (int ni = 0; ni < 4; ni++) {
        const int gc = col0 + wn * 32 + ni * 8 + (lane & 3) * 2;
        bv0[ni] = __ldg(&bias1[gc]);
        bv1[ni] = __ldg(&bias1[gc + 1]);
        if (DUAL) {
            bv0[ni] += __ldg(&bias2[gc]);
            bv1[ni] += __ldg(&bias2[gc + 1]);
        }
    }

#pragma unroll
    for (int mi = 0; mi < 4; mi++) {
        const int gr = row0 + wm * 64 + mi * 16 + (lane >> 2);
#pragma unroll
        for (int ni = 0; ni < 4; ni++) {
            const int gc = col0 + wn * 32 + ni * 8 + (lane & 3) * 2;
#pragma unroll
            for (int half = 0; half < 2; half++) {
                const int r  = gr + half * 8;
                float v0 = acc[mi][ni][half * 2 + 0] + bv0[ni];
                float v1 = acc[mi][ni][half * 2 + 1] + bv1[ni];
                if (GATES) {
                    // v = hh (pre-activation).  channel = gc (N==Cch here)
                    const float2 zs = *(const float2*)&gzr[(size_t)r * C2 + gc];
                    const float2 rs = *(const float2*)&gzr[(size_t)r * C2 + Cch + gc];
                    const float2 xv = *(const float2*)&xh [(size_t)r * Cch + gc];
                    const float2 hv = *(const float2*)&ann[(size_t)r * Cch + gc];
                    const float z0 = sigf(zs.x), z1 = sigf(zs.y);
                    const float r0 = sigf(rs.x), r1 = sigf(rs.y);
                    const float h0 = tanhfast(xv.x + r0 * v0);
                    const float h1 = tanhfast(xv.y + r1 * v1);
                    v0 = z0 * hv.x + (1.f - z0) * h0;
                    v1 = z1 * hv.y + (1.f - z1) * h1;
                }
                *(float2*)&C[(size_t)r * ldc + gc] = make_float2(v0, v1);
            }
        }
    }
}

// ---------------------------------------------------------------- launch
extern "C" void kernel_launch(void* const* d_in, const int* in_sizes, int n_in,
                              void* d_out, int out_size)
{
    const float* adj = (const float*)d_in[0];
    const float* ann = (const float*)d_in[1];
    const float* gcb = (const float*)d_in[2];
    const float* W   = (const float*)d_in[3];  // [512,1536]
    const float* U   = (const float*)d_in[4];  // [512,1536]
    const float* gb  = (const float*)d_in[5];  // [2,1536]
    const float* dW  = (const float*)d_in[6];  // [512,256]
    const float* db  = (const float*)d_in[7];  // [256]
    float* out = (float*)d_out;

    float *msg, *gzr, *xh, *hnew;
    cudaGetSymbolAddress((void**)&msg,  g_msg);
    cudaGetSymbolAddress((void**)&gzr,  g_gzr);
    cudaGetSymbolAddress((void**)&xh,   g_xh);
    cudaGetSymbolAddress((void**)&hnew, g_hnew);

    cudaFuncSetAttribute(gemm_k<false,false>, cudaFuncAttributeMaxDynamicSharedMemorySize, SMEM_BYTES);
    cudaFuncSetAttribute(gemm_k<true, false>, cudaFuncAttributeMaxDynamicSharedMemorySize, SMEM_BYTES);
    cudaFuncSetAttribute(gemm_k<false,true >, cudaFuncAttributeMaxDynamicSharedMemorySize, SMEM_BYTES);

    const dim3 blk(256);

    // 1) msg = bmm(adjacent, annotations) + gc_bias        (K=256 -> T=8)
    gemm_k<false,false><<<dim3(Cch / BN, Nn / BM, Bb), blk, SMEM_BYTES>>>(
        adj, ann, Nn / BK, nullptr, nullptr, 0,
        msg, gcb, nullptr,
        Nn, Cch, Cch,
        (long long)Nn * Nn, (long long)Nn * Cch, (long long)Nn * Cch,
        nullptr, nullptr, nullptr);

    // 2) gzr = msg@W[:,0:1024] + ann@U[:,0:1024] + b0 + b1 (dual K: 16+16)
    gemm_k<true,false><<<dim3(C2 / BN, MR / BM, 1), blk, SMEM_BYTES>>>(
        msg, W, Cch / BK, ann, U, Cch / BK,
        gzr, gb, gb + C3,
        Cch, C3, C2, 0, 0, 0,
        nullptr, nullptr, nullptr);

    // 3) xh = msg@W[:,1024:1536] + b0[1024:]
    gemm_k<false,false><<<dim3(Cch / BN, MR / BM, 1), blk, SMEM_BYTES>>>(
        msg, W + C2, Cch / BK, nullptr, nullptr, 0,
        xh, gb + C2, nullptr,
        Cch, C3, Cch, 0, 0, 0,
        nullptr, nullptr, nullptr);

    // 4) hnew = gate( gzr, xh, ann@U[:,1024:]+b1[1024:], ann )  (fused epilogue)
    gemm_k<false,true><<<dim3(Cch / BN, MR / BM, 1), blk, SMEM_BYTES>>>(
        ann, U + C2, Cch / BK, nullptr, nullptr, 0,
        hnew, gb + C3 + C2, nullptr,
        Cch, C3, Cch, 0, 0, 0,
        gzr, xh, ann);

    // 5) out = hnew @ dense_W + dense_b
    gemm_k<false,false><<<dim3(Oo / BN, MR / BM, 1), blk, SMEM_BYTES>>>(
        hnew, dW, Cch / BK, nullptr, nullptr, 0,
        out, db, nullptr,
        Cch, Oo, Oo, 0, 0, 0,
        nullptr, nullptr, nullptr);
}